// round 8
// baseline (speedup 1.0000x reference)
#include <cuda_runtime.h>
#include <cstdint>

#define N_NODES 50000
#define N_EDGES 600000
#define DIM 128
#define TOT_EDGES (N_EDGES + N_NODES)   // edges + self loops
#define NB 196                          // ceil(50000/256) scan blocks

// A tile: 128 rows x 132 words (pad 4), W chunk: 128 n x 36 words (pad 4)
#define A_STRIDE 132
#define W_STRIDE 36
#define SMEM_BYTES ((128 * A_STRIDE + 128 * W_STRIDE) * 4)

// ---- scratch (device globals; no allocations allowed) ----
__device__ float g_hw0 [N_NODES * DIM];  // hw ping
__device__ float g_hw1 [N_NODES * DIM];  // hw pong
__device__ float g_dinv[N_NODES];        // rsqrt(deg)
__device__ int   g_deg   [N_NODES];
__device__ int   g_rowptr[N_NODES + 1];
__device__ int   g_cursor[N_NODES];
__device__ int   g_bsum  [NB];
__device__ int   g_esrc  [TOT_EDGES];    // CSR-by-dst: src node per slot
__device__ float g_enorm [TOT_EDGES];    // dinv[src]*dinv[dst] per slot

// ---------------------------------------------------------------------------
// CSR build: degree -> block sums -> finalize (inline top-scan) -> fill
// ---------------------------------------------------------------------------
__global__ void deg_init_k() {
    int i = blockIdx.x * blockDim.x + threadIdx.x;
    if (i < N_NODES) g_deg[i] = 1;          // self loop
}

__global__ void deg_count_k(const int* __restrict__ ei) {
    int e = blockIdx.x * blockDim.x + threadIdx.x;
    if (e < N_EDGES) {
        int d = ei[N_EDGES + e];
        if (d >= 0 && d < N_NODES) atomicAdd(&g_deg[d], 1);
    }
}

__global__ void __launch_bounds__(256) bsum_k() {
    __shared__ int sh[256];
    int i = blockIdx.x * 256 + threadIdx.x;
    sh[threadIdx.x] = (i < N_NODES) ? g_deg[i] : 0;
    __syncthreads();
    for (int off = 128; off > 0; off >>= 1) {
        if (threadIdx.x < off) sh[threadIdx.x] += sh[threadIdx.x + off];
        __syncthreads();
    }
    if (threadIdx.x == 0) g_bsum[blockIdx.x] = sh[0];
}

__global__ void __launch_bounds__(256) finalize_k() {
    __shared__ int sh[256];
    __shared__ int blkoff;
    int i = blockIdx.x * 256 + threadIdx.x;
    int t = threadIdx.x;

    // offset of this block = sum of bsum[j] for j < blockIdx.x
    sh[t] = (t < NB && t < blockIdx.x) ? g_bsum[t] : 0;
    __syncthreads();
    for (int off = 128; off > 0; off >>= 1) {
        if (t < off) sh[t] += sh[t + off];
        __syncthreads();
    }
    if (t == 0) blkoff = sh[0];
    __syncthreads();

    // intra-block inclusive scan of degrees
    int v = (i < N_NODES) ? g_deg[i] : 0;
    sh[t] = v;
    __syncthreads();
    for (int off = 1; off < 256; off <<= 1) {
        int x = (t >= off) ? sh[t - off] : 0;
        __syncthreads();
        sh[t] += x;
        __syncthreads();
    }
    if (i < N_NODES) {
        int start = blkoff + sh[t] - v;     // exclusive global prefix
        g_rowptr[i] = start;
        g_cursor[i] = start;
        g_dinv[i]   = rsqrtf((float)v);
        if (i == N_NODES - 1) g_rowptr[N_NODES] = start + v;
    }
}

__global__ void fill_k(const int* __restrict__ ei) {
    int e = blockIdx.x * blockDim.x + threadIdx.x;
    if (e >= TOT_EDGES) return;
    int s, d;
    if (e < N_EDGES) {
        s = ei[e];
        d = ei[N_EDGES + e];
        if (s < 0 || s >= N_NODES || d < 0 || d >= N_NODES) return;
    } else {
        s = d = e - N_EDGES;                // self loop
    }
    int pos = atomicAdd(&g_cursor[d], 1);
    g_esrc[pos]  = s;
    g_enorm[pos] = g_dinv[s] * g_dinv[d];
}

// ---------------------------------------------------------------------------
// fused layer kernel:
//   mode 0: A = x (external), no gather/relu;  writes g_hw0
//   mode 1: A = relu(gather(g_hw0) + bias);    writes g_hw1
//   mode 2: A = relu(gather(g_hw1) + bias);    writes g_hw0
// then hw_dst[rows,128] = A @ W  via mma.m16n8k8.tf32
// 256 threads, block tile 128x128; 8 warps (4M x 2N), warp tile 32x64.
// Full-K A tile in dynamic smem; W staged in 32-k chunks.
// ---------------------------------------------------------------------------
__device__ __forceinline__ uint32_t f2tf32(float f) {
    uint32_t r;
    asm("cvt.rna.tf32.f32 %0, %1;" : "=r"(r) : "f"(f));
    return r;
}

extern __shared__ uint32_t s_dyn[];

__global__ void __launch_bounds__(256) fused_layer_k(
    const float* __restrict__ x, const float* __restrict__ W,
    const float* __restrict__ bias, int mode)
{
    uint32_t* As = s_dyn;                    // [128][A_STRIDE]
    uint32_t* Wt = s_dyn + 128 * A_STRIDE;   // [128 n][W_STRIDE]

    const int tid   = threadIdx.x;
    const int lane  = tid & 31;
    const int wid   = tid >> 5;
    const int warpM = wid & 3;
    const int warpN = wid >> 2;
    const int g     = lane >> 2;
    const int q     = lane & 3;
    const int row0  = blockIdx.x * 128;

    const float* gsrc = (mode == 2) ? g_hw1 : g_hw0;
    float*       gdst = (mode == 1) ? g_hw1 : g_hw0;

    // ---- A phase ----
    if (mode == 0) {
        // plain load of x rows (tf32 convert), 16 float4 per thread
#pragma unroll
        for (int t = 0; t < 16; t++) {
            int i  = tid + t * 256;          // 0..4095
            int r  = i >> 5;                 // 0..127
            int c4 = (i & 31) * 4;           // 0..124
            int grow = row0 + r;
            float4 v = make_float4(0.f, 0.f, 0.f, 0.f);
            if (grow < N_NODES)
                v = *(const float4*)(x + (size_t)grow * DIM + c4);
            uint4 p;
            p.x = f2tf32(v.x); p.y = f2tf32(v.y);
            p.z = f2tf32(v.z); p.w = f2tf32(v.w);
            *(uint4*)&As[r * A_STRIDE + c4] = p;
        }
    } else {
        // gather: each warp produces 16 rows; lane owns float4 #lane
        const float4* src4 = (const float4*)gsrc;
        float4 b4 = ((const float4*)bias)[lane];
        for (int rr = 0; rr < 16; rr++) {
            int row  = wid * 16 + rr;
            int grow = row0 + row;
            float4 acc = make_float4(0.f, 0.f, 0.f, 0.f);
            if (grow < N_NODES) {
                acc = b4;
                int j   = g_rowptr[grow];
                int end = g_rowptr[grow + 1];
                for (; j + 1 < end; j += 2) {
                    int   s0 = g_esrc[j],  s1 = g_esrc[j + 1];
                    float n0 = g_enorm[j], n1 = g_enorm[j + 1];
                    float4 v0 = src4[s0 * 32 + lane];
                    float4 v1 = src4[s1 * 32 + lane];
                    acc.x += v0.x * n0; acc.y += v0.y * n0;
                    acc.z += v0.z * n0; acc.w += v0.w * n0;
                    acc.x += v1.x * n1; acc.y += v1.y * n1;
                    acc.z += v1.z * n1; acc.w += v1.w * n1;
                }
                if (j < end) {
                    int   s0 = g_esrc[j];
                    float n0 = g_enorm[j];
                    float4 v0 = src4[s0 * 32 + lane];
                    acc.x += v0.x * n0; acc.y += v0.y * n0;
                    acc.z += v0.z * n0; acc.w += v0.w * n0;
                }
                acc.x = fmaxf(acc.x, 0.f); acc.y = fmaxf(acc.y, 0.f);
                acc.z = fmaxf(acc.z, 0.f); acc.w = fmaxf(acc.w, 0.f);
            }
            uint4 p;
            p.x = f2tf32(acc.x); p.y = f2tf32(acc.y);
            p.z = f2tf32(acc.z); p.w = f2tf32(acc.w);
            *(uint4*)&As[row * A_STRIDE + lane * 4] = p;
        }
    }
    __syncthreads();

    // ---- mma phase: 4 W chunks of 32 k ----
    float acc[2][8][4];
#pragma unroll
    for (int mt = 0; mt < 2; mt++)
#pragma unroll
        for (int nt = 0; nt < 8; nt++)
#pragma unroll
            for (int i = 0; i < 4; i++) acc[mt][nt][i] = 0.0f;

    for (int c = 0; c < 4; ++c) {
        // load W chunk transposed: Wt[n][k], k in [c*32, c*32+32)
#pragma unroll
        for (int t = 0; t < 4; t++) {
            int i  = tid + t * 256;          // 0..1023
            int kr = i >> 5;                 // 0..31
            int c4 = (i & 31) * 4;           // 0..124
            float4 w = *(const float4*)(W + (size_t)(c * 32 + kr) * DIM + c4);
            Wt[(c4 + 0) * W_STRIDE + kr] = f2tf32(w.x);
            Wt[(c4 + 1) * W_STRIDE + kr] = f2tf32(w.y);
            Wt[(c4 + 2) * W_STRIDE + kr] = f2tf32(w.z);
            Wt[(c4 + 3) * W_STRIDE + kr] = f2tf32(w.w);
        }
        __syncthreads();

#pragma unroll
        for (int ks = 0; ks < 4; ++ks) {
            const int kk = c * 32 + ks * 8;  // global k for As
            const int kw = ks * 8;           // k within W chunk

            uint32_t a[2][4];
#pragma unroll
            for (int mt = 0; mt < 2; mt++) {
                int mb = warpM * 32 + mt * 16 + g;
                a[mt][0] = As[mb * A_STRIDE + kk + q];
                a[mt][1] = As[(mb + 8) * A_STRIDE + kk + q];
                a[mt][2] = As[mb * A_STRIDE + kk + q + 4];
                a[mt][3] = As[(mb + 8) * A_STRIDE + kk + q + 4];
            }
            uint32_t b[8][2];
#pragma unroll
            for (int nt = 0; nt < 8; nt++) {
                int n = warpN * 64 + nt * 8 + g;
                b[nt][0] = Wt[n * W_STRIDE + kw + q];
                b[nt][1] = Wt[n * W_STRIDE + kw + q + 4];
            }
#pragma unroll
            for (int mt = 0; mt < 2; mt++)
#pragma unroll
                for (int nt = 0; nt < 8; nt++) {
                    asm volatile(
                        "mma.sync.aligned.m16n8k8.row.col.f32.tf32.tf32.f32 "
                        "{%0,%1,%2,%3}, {%4,%5,%6,%7}, {%8,%9}, {%0,%1,%2,%3};"
                        : "+f"(acc[mt][nt][0]), "+f"(acc[mt][nt][1]),
                          "+f"(acc[mt][nt][2]), "+f"(acc[mt][nt][3])
                        : "r"(a[mt][0]), "r"(a[mt][1]), "r"(a[mt][2]), "r"(a[mt][3]),
                          "r"(b[nt][0]), "r"(b[nt][1]));
                }
        }
        __syncthreads();
    }

    // ---- epilogue ----
#pragma unroll
    for (int mt = 0; mt < 2; mt++) {
        int r0 = row0 + warpM * 32 + mt * 16 + g;
        int r1 = r0 + 8;
#pragma unroll
        for (int nt = 0; nt < 8; nt++) {
            int col = warpN * 64 + nt * 8 + q * 2;
            if (r0 < N_NODES)
                *(float2*)(gdst + (size_t)r0 * DIM + col) =
                    make_float2(acc[mt][nt][0], acc[mt][nt][1]);
            if (r1 < N_NODES)
                *(float2*)(gdst + (size_t)r1 * DIM + col) =
                    make_float2(acc[mt][nt][2], acc[mt][nt][3]);
        }
    }
}

// ---------------------------------------------------------------------------
// final gather: warp per dst node; out = relu(gather(g_hw0) + b2)
// ---------------------------------------------------------------------------
__global__ void __launch_bounds__(256) gather_out_k(
    const float* __restrict__ bias, float* __restrict__ out)
{
    int w    = (blockIdx.x * blockDim.x + threadIdx.x) >> 5;
    int lane = threadIdx.x & 31;
    if (w >= N_NODES) return;

    int beg = g_rowptr[w];
    int end = g_rowptr[w + 1];

    float4 acc = ((const float4*)bias)[lane];
    const float4* hw4 = (const float4*)g_hw0;

    int j = beg;
    for (; j + 1 < end; j += 2) {
        int   s0 = g_esrc[j],  s1 = g_esrc[j + 1];
        float n0 = g_enorm[j], n1 = g_enorm[j + 1];
        float4 v0 = hw4[s0 * 32 + lane];
        float4 v1 = hw4[s1 * 32 + lane];
        acc.x += v0.x * n0; acc.y += v0.y * n0;
        acc.z += v0.z * n0; acc.w += v0.w * n0;
        acc.x += v1.x * n1; acc.y += v1.y * n1;
        acc.z += v1.z * n1; acc.w += v1.w * n1;
    }
    if (j < end) {
        int   s0 = g_esrc[j];
        float n0 = g_enorm[j];
        float4 v0 = hw4[s0 * 32 + lane];
        acc.x += v0.x * n0; acc.y += v0.y * n0;
        acc.z += v0.z * n0; acc.w += v0.w * n0;
    }

    acc.x = fmaxf(acc.x, 0.f); acc.y = fmaxf(acc.y, 0.f);
    acc.z = fmaxf(acc.z, 0.f); acc.w = fmaxf(acc.w, 0.f);
    ((float4*)out)[w * 32 + lane] = acc;
}

// ---------------------------------------------------------------------------
extern "C" void kernel_launch(void* const* d_in, const int* in_sizes, int n_in,
                              void* d_out, int out_size)
{
    const float* x  = (const float*)d_in[0];
    const int*   ei = (const int*)d_in[1];     // edge_index int32 [2, E]
    const float* W0 = (const float*)d_in[2];
    const float* b0 = (const float*)d_in[3];
    const float* W1 = (const float*)d_in[4];
    const float* b1 = (const float*)d_in[5];
    const float* W2 = (const float*)d_in[6];
    const float* b2 = (const float*)d_in[7];
    float* out = (float*)d_out;

    static int smem_set = 0;
    if (!smem_set) {
        cudaFuncSetAttribute(fused_layer_k,
            cudaFuncAttributeMaxDynamicSharedMemorySize, SMEM_BYTES);
        smem_set = 1;
    }

    const int edgeBlocks = (N_EDGES + 255) / 256;
    const int totBlocks  = (TOT_EDGES + 255) / 256;
    const int gemmBlocks = (N_NODES + 127) / 128;
    const int gathBlocks = (N_NODES * 32 + 255) / 256;

    // CSR build (once; reused by all layers)
    deg_init_k <<<NB, 256>>>();
    deg_count_k<<<edgeBlocks, 256>>>(ei);
    bsum_k     <<<NB, 256>>>();
    finalize_k <<<NB, 256>>>();
    fill_k     <<<totBlocks, 256>>>(ei);

    // layer 0: g_hw0 = x @ W0
    fused_layer_k<<<gemmBlocks, 256, SMEM_BYTES>>>(x, W0, b0, 0);
    // layer 1: g_hw1 = relu(gather(g_hw0)+b0) @ W1
    fused_layer_k<<<gemmBlocks, 256, SMEM_BYTES>>>(x, W1, b0, 1);
    // layer 2: g_hw0 = relu(gather(g_hw1)+b1) @ W2
    fused_layer_k<<<gemmBlocks, 256, SMEM_BYTES>>>(x, W2, b1, 2);
    // out = relu(gather(g_hw0) + b2)
    gather_out_k<<<gathBlocks, 256>>>(b2, out);
}

// round 9
// speedup vs baseline: 1.3667x; 1.3667x over previous
#include <cuda_runtime.h>
#include <cuda_fp16.h>
#include <cstdint>

#define N_NODES 50000
#define N_EDGES 600000
#define DIM 128
#define TOT_EDGES (N_EDGES + N_NODES)   // edges + self loops
#define NB 196                          // ceil(50000/256) scan blocks

// ---- scratch (device globals; no allocations allowed) ----
__device__ __half g_hw  [N_NODES * DIM];  // h @ W          (fp16)
__device__ __half g_act [N_NODES * DIM];  // relu(agg + b)  (fp16)
__device__ float  g_dinv[N_NODES];
__device__ int    g_deg   [N_NODES];
__device__ int    g_rowptr[N_NODES + 1];
__device__ int    g_cursor[N_NODES];
__device__ int    g_bsum  [NB];
__device__ int    g_esrc  [TOT_EDGES];    // CSR-by-dst: src node per slot
__device__ float  g_enorm [TOT_EDGES];    // dinv[src]*dinv[dst] per slot

// ---------------------------------------------------------------------------
// CSR build: degree -> block sums -> finalize (inline top-scan) -> fill
// ---------------------------------------------------------------------------
__global__ void deg_init_k() {
    int i = blockIdx.x * blockDim.x + threadIdx.x;
    if (i < N_NODES) g_deg[i] = 1;          // self loop
}

__global__ void deg_count_k(const int* __restrict__ ei) {
    int e = blockIdx.x * blockDim.x + threadIdx.x;
    if (e < N_EDGES) {
        int d = ei[N_EDGES + e];
        if (d >= 0 && d < N_NODES) atomicAdd(&g_deg[d], 1);
    }
}

__global__ void __launch_bounds__(256) bsum_k() {
    __shared__ int sh[256];
    int i = blockIdx.x * 256 + threadIdx.x;
    sh[threadIdx.x] = (i < N_NODES) ? g_deg[i] : 0;
    __syncthreads();
    for (int off = 128; off > 0; off >>= 1) {
        if (threadIdx.x < off) sh[threadIdx.x] += sh[threadIdx.x + off];
        __syncthreads();
    }
    if (threadIdx.x == 0) g_bsum[blockIdx.x] = sh[0];
}

__global__ void __launch_bounds__(256) finalize_k() {
    __shared__ int sh[256];
    __shared__ int blkoff;
    int i = blockIdx.x * 256 + threadIdx.x;
    int t = threadIdx.x;

    // offset of this block = sum of bsum[j] for j < blockIdx.x
    sh[t] = (t < NB && t < blockIdx.x) ? g_bsum[t] : 0;
    __syncthreads();
    for (int off = 128; off > 0; off >>= 1) {
        if (t < off) sh[t] += sh[t + off];
        __syncthreads();
    }
    if (t == 0) blkoff = sh[0];
    __syncthreads();

    // intra-block inclusive scan of degrees
    int v = (i < N_NODES) ? g_deg[i] : 0;
    sh[t] = v;
    __syncthreads();
    for (int off = 1; off < 256; off <<= 1) {
        int x = (t >= off) ? sh[t - off] : 0;
        __syncthreads();
        sh[t] += x;
        __syncthreads();
    }
    if (i < N_NODES) {
        int start = blkoff + sh[t] - v;     // exclusive global prefix
        g_rowptr[i] = start;
        g_cursor[i] = start;
        g_dinv[i]   = rsqrtf((float)v);
        if (i == N_NODES - 1) g_rowptr[N_NODES] = start + v;
    }
}

__global__ void fill_k(const int* __restrict__ ei) {
    int e = blockIdx.x * blockDim.x + threadIdx.x;
    if (e >= TOT_EDGES) return;
    int s, d;
    if (e < N_EDGES) {
        s = ei[e];
        d = ei[N_EDGES + e];
        if (s < 0 || s >= N_NODES || d < 0 || d >= N_NODES) return;
    } else {
        s = d = e - N_EDGES;                // self loop
    }
    int pos = atomicAdd(&g_cursor[d], 1);
    g_esrc[pos]  = s;
    g_enorm[pos] = g_dinv[s] * g_dinv[d];
}

// ---------------------------------------------------------------------------
// tf32 tensor-core GEMM: g_hw[N,128] (fp16) = src @ W[128,128]
//   use_agg=0: src = x (fp32 input);  use_agg=1: src = g_act (fp16, pre-relu'd)
// 128x128 block tile, 8 warps (4M x 2N), warp tile 32x64, mma.m16n8k8.tf32
// ---------------------------------------------------------------------------
__device__ __forceinline__ uint32_t f2tf32(float f) {
    uint32_t r;
    asm("cvt.rna.tf32.f32 %0, %1;" : "=r"(r) : "f"(f));
    return r;
}

__global__ void __launch_bounds__(256) gemm_tf32_k(
    const float* __restrict__ A, const float* __restrict__ W, int use_agg)
{
    __shared__ uint32_t As[128 * 36];   // [m][k] chunk, pad 36
    __shared__ uint32_t Wt[128 * 36];   // [n][k] chunk (transposed), pad 36

    const int tid   = threadIdx.x;
    const int lane  = tid & 31;
    const int wid   = tid >> 5;
    const int warpM = wid & 3;          // 0..3  -> 32-row strip
    const int warpN = wid >> 2;         // 0..1  -> 64-col strip
    const int g     = lane >> 2;        // groupID 0..7
    const int q     = lane & 3;         // thread-in-group 0..3
    const int row0  = blockIdx.x * 128;

    float acc[2][8][4];
#pragma unroll
    for (int mt = 0; mt < 2; mt++)
#pragma unroll
        for (int nt = 0; nt < 8; nt++)
#pragma unroll
            for (int i = 0; i < 4; i++) acc[mt][nt][i] = 0.0f;

    for (int c = 0; c < 4; ++c) {       // K chunks of 32
        // ---- load A chunk: 128 rows x 32 k ----
        if (!use_agg) {
#pragma unroll
            for (int t = 0; t < 4; t++) {
                int i  = tid + t * 256;     // 0..1023
                int r  = i >> 3;            // 0..127
                int c4 = (i & 7) * 4;       // 0..28
                int grow = row0 + r;
                float4 v = make_float4(0.f, 0.f, 0.f, 0.f);
                if (grow < N_NODES)
                    v = *(const float4*)(A + (size_t)grow * DIM + c * 32 + c4);
                uint32_t* p = &As[r * 36 + c4];
                p[0] = f2tf32(v.x); p[1] = f2tf32(v.y);
                p[2] = f2tf32(v.z); p[3] = f2tf32(v.w);
            }
        } else {
            // fp16 source (already relu'd): 8 halves per thread, 2 iters
#pragma unroll
            for (int t = 0; t < 2; t++) {
                int i  = tid + t * 256;     // 0..511
                int r  = i >> 2;            // 0..127
                int c8 = (i & 3) * 8;       // 0,8,16,24
                int grow = row0 + r;
                uint4 raw = make_uint4(0, 0, 0, 0);
                if (grow < N_NODES)
                    raw = *(const uint4*)(g_act + (size_t)grow * DIM + c * 32 + c8);
                float2 f0 = __half22float2(*(__half2*)&raw.x);
                float2 f1 = __half22float2(*(__half2*)&raw.y);
                float2 f2 = __half22float2(*(__half2*)&raw.z);
                float2 f3 = __half22float2(*(__half2*)&raw.w);
                uint32_t* p = &As[r * 36 + c8];
                p[0] = f2tf32(f0.x); p[1] = f2tf32(f0.y);
                p[2] = f2tf32(f1.x); p[3] = f2tf32(f1.y);
                p[4] = f2tf32(f2.x); p[5] = f2tf32(f2.y);
                p[6] = f2tf32(f3.x); p[7] = f2tf32(f3.y);
            }
        }
        // ---- load W chunk transposed: Wt[n][k], 32 k-rows x 128 n ----
#pragma unroll
        for (int t = 0; t < 4; t++) {
            int i  = tid + t * 256;     // 0..1023
            int kr = i >> 5;            // 0..31
            int c4 = (i & 31) * 4;      // 0..124
            float4 w = *(const float4*)(W + (size_t)(c * 32 + kr) * DIM + c4);
            Wt[(c4 + 0) * 36 + kr] = f2tf32(w.x);
            Wt[(c4 + 1) * 36 + kr] = f2tf32(w.y);
            Wt[(c4 + 2) * 36 + kr] = f2tf32(w.z);
            Wt[(c4 + 3) * 36 + kr] = f2tf32(w.w);
        }
        __syncthreads();

#pragma unroll
        for (int ks = 0; ks < 4; ++ks) {    // 4 k-steps of 8 within chunk
            const int kk = ks * 8;

            uint32_t a[2][4];
#pragma unroll
            for (int mt = 0; mt < 2; mt++) {
                int mb = warpM * 32 + mt * 16 + g;
                a[mt][0] = As[mb * 36 + kk + q];
                a[mt][1] = As[(mb + 8) * 36 + kk + q];
                a[mt][2] = As[mb * 36 + kk + q + 4];
                a[mt][3] = As[(mb + 8) * 36 + kk + q + 4];
            }
            uint32_t b[8][2];
#pragma unroll
            for (int nt = 0; nt < 8; nt++) {
                int n = warpN * 64 + nt * 8 + g;
                b[nt][0] = Wt[n * 36 + kk + q];
                b[nt][1] = Wt[n * 36 + kk + q + 4];
            }
#pragma unroll
            for (int mt = 0; mt < 2; mt++)
#pragma unroll
                for (int nt = 0; nt < 8; nt++) {
                    asm volatile(
                        "mma.sync.aligned.m16n8k8.row.col.f32.tf32.tf32.f32 "
                        "{%0,%1,%2,%3}, {%4,%5,%6,%7}, {%8,%9}, {%0,%1,%2,%3};"
                        : "+f"(acc[mt][nt][0]), "+f"(acc[mt][nt][1]),
                          "+f"(acc[mt][nt][2]), "+f"(acc[mt][nt][3])
                        : "r"(a[mt][0]), "r"(a[mt][1]), "r"(a[mt][2]), "r"(a[mt][3]),
                          "r"(b[nt][0]), "r"(b[nt][1]));
                }
        }
        __syncthreads();
    }

    // ---- epilogue: write fp16 hw ----
#pragma unroll
    for (int mt = 0; mt < 2; mt++) {
        int r0 = row0 + warpM * 32 + mt * 16 + g;
        int r1 = r0 + 8;
#pragma unroll
        for (int nt = 0; nt < 8; nt++) {
            int col = warpN * 64 + nt * 8 + q * 2;
            if (r0 < N_NODES) {
                __half2 h = __float22half2_rn(
                    make_float2(acc[mt][nt][0], acc[mt][nt][1]));
                *(__half2*)(g_hw + (size_t)r0 * DIM + col) = h;
            }
            if (r1 < N_NODES) {
                __half2 h = __float22half2_rn(
                    make_float2(acc[mt][nt][2], acc[mt][nt][3]));
                *(__half2*)(g_hw + (size_t)r1 * DIM + col) = h;
            }
        }
    }
}

// ---------------------------------------------------------------------------
// gather: warp per dst node; lane owns 4 halves (8B) of the 256B row.
// acc = bias; acc += hw[src]*norm (fp32 math); relu;
// last=0 -> write fp16 g_act; last=1 -> write fp32 out.
// ---------------------------------------------------------------------------
__global__ void __launch_bounds__(256) gather_k(
    const float* __restrict__ bias, float* __restrict__ out, int last)
{
    int w    = (blockIdx.x * blockDim.x + threadIdx.x) >> 5;
    int lane = threadIdx.x & 31;
    if (w >= N_NODES) return;

    int beg = g_rowptr[w];
    int end = g_rowptr[w + 1];

    float4 acc = ((const float4*)bias)[lane];
    const uint2* hw2 = (const uint2*)g_hw;   // 4 halves per lane-slot

    int j = beg;
    for (; j + 3 < end; j += 4) {
        int   s0 = g_esrc[j],      s1 = g_esrc[j + 1];
        int   s2 = g_esrc[j + 2],  s3 = g_esrc[j + 3];
        float n0 = g_enorm[j],     n1 = g_enorm[j + 1];
        float n2 = g_enorm[j + 2], n3 = g_enorm[j + 3];
        uint2 r0 = hw2[s0 * 32 + lane];
        uint2 r1 = hw2[s1 * 32 + lane];
        uint2 r2 = hw2[s2 * 32 + lane];
        uint2 r3 = hw2[s3 * 32 + lane];
        float2 a0 = __half22float2(*(__half2*)&r0.x), b0 = __half22float2(*(__half2*)&r0.y);
        float2 a1 = __half22float2(*(__half2*)&r1.x), b1 = __half22float2(*(__half2*)&r1.y);
        float2 a2 = __half22float2(*(__half2*)&r2.x), b2 = __half22float2(*(__half2*)&r2.y);
        float2 a3 = __half22float2(*(__half2*)&r3.x), b3 = __half22float2(*(__half2*)&r3.y);
        acc.x += a0.x * n0; acc.y += a0.y * n0; acc.z += b0.x * n0; acc.w += b0.y * n0;
        acc.x += a1.x * n1; acc.y += a1.y * n1; acc.z += b1.x * n1; acc.w += b1.y * n1;
        acc.x += a2.x * n2; acc.y += a2.y * n2; acc.z += b2.x * n2; acc.w += b2.y * n2;
        acc.x += a3.x * n3; acc.y += a3.y * n3; acc.z += b3.x * n3; acc.w += b3.y * n3;
    }
    for (; j < end; j++) {
        int   s0 = g_esrc[j];
        float n0 = g_enorm[j];
        uint2 r0 = hw2[s0 * 32 + lane];
        float2 a0 = __half22float2(*(__half2*)&r0.x), b0 = __half22float2(*(__half2*)&r0.y);
        acc.x += a0.x * n0; acc.y += a0.y * n0; acc.z += b0.x * n0; acc.w += b0.y * n0;
    }

    acc.x = fmaxf(acc.x, 0.f); acc.y = fmaxf(acc.y, 0.f);
    acc.z = fmaxf(acc.z, 0.f); acc.w = fmaxf(acc.w, 0.f);

    if (last) {
        ((float4*)out)[w * 32 + lane] = acc;
    } else {
        uint2 o;
        *(__half2*)&o.x = __float22half2_rn(make_float2(acc.x, acc.y));
        *(__half2*)&o.y = __float22half2_rn(make_float2(acc.z, acc.w));
        ((uint2*)g_act)[w * 32 + lane] = o;
    }
}

// ---------------------------------------------------------------------------
extern "C" void kernel_launch(void* const* d_in, const int* in_sizes, int n_in,
                              void* d_out, int out_size)
{
    const float* x  = (const float*)d_in[0];
    const int*   ei = (const int*)d_in[1];     // edge_index int32 [2, E]
    const float* W0 = (const float*)d_in[2];
    const float* b0 = (const float*)d_in[3];
    const float* W1 = (const float*)d_in[4];
    const float* b1 = (const float*)d_in[5];
    const float* W2 = (const float*)d_in[6];
    const float* b2 = (const float*)d_in[7];
    float* out = (float*)d_out;

    const int edgeBlocks = (N_EDGES + 255) / 256;
    const int totBlocks  = (TOT_EDGES + 255) / 256;
    const int gemmBlocks = (N_NODES + 127) / 128;
    const int gathBlocks = (N_NODES * 32 + 255) / 256;   // warp per node

    // CSR build (once; reused by all 3 layers)
    deg_init_k <<<NB, 256>>>();
    deg_count_k<<<edgeBlocks, 256>>>(ei);
    bsum_k     <<<NB, 256>>>();
    finalize_k <<<NB, 256>>>();
    fill_k     <<<totBlocks, 256>>>(ei);

    // layer 0: hw = x @ W0 ; act = relu(gather(hw) + b0)
    gemm_tf32_k<<<gemmBlocks, 256>>>(x, W0, 0);
    gather_k   <<<gathBlocks, 256>>>(b0, out, 0);
    // layer 1: hw = act @ W1 ; act = relu(gather(hw) + b1)
    gemm_tf32_k<<<gemmBlocks, 256>>>(x, W1, 1);
    gather_k   <<<gathBlocks, 256>>>(b1, out, 0);
    // layer 2: hw = act @ W2 ; out = relu(gather(hw) + b2)
    gemm_tf32_k<<<gemmBlocks, 256>>>(x, W2, 1);
    gather_k   <<<gathBlocks, 256>>>(b2, out, 1);
}

// round 10
// speedup vs baseline: 1.9764x; 1.4461x over previous
#include <cuda_runtime.h>
#include <cuda_fp16.h>
#include <cstdint>

#define N_NODES 50000
#define N_EDGES 600000
#define DIM 128
#define TOT_EDGES (N_EDGES + N_NODES)   // edges + self loops
#define NB 196                          // ceil(50000/256) scan blocks

// smem tiles: halves, row stride 136 (272B = 16B-aligned, conflict-free frags)
#define STRH 136                        // stride in halves
#define STRW 68                         // stride in u32 words
#define SMEM_BYTES (2 * 128 * STRH * 2) // As + Wt = 69632 B

// ---- scratch (device globals; no allocations allowed) ----
__device__ __half g_hw  [N_NODES * DIM];  // h @ W          (fp16)
__device__ __half g_act [N_NODES * DIM];  // relu(agg + b)  (fp16)
__device__ float  g_dinv[N_NODES];
__device__ int    g_deg   [N_NODES];
__device__ int    g_rowptr[N_NODES + 1];
__device__ int    g_cursor[N_NODES];
__device__ int    g_bsum  [NB];
__device__ int    g_esrc  [TOT_EDGES];    // CSR-by-dst: src node per slot
__device__ float  g_enorm [TOT_EDGES];    // dinv[src]*dinv[dst] per slot

// ---------------------------------------------------------------------------
// CSR build: degree -> block sums -> finalize (inline top-scan) -> fill
// ---------------------------------------------------------------------------
__global__ void deg_init_k() {
    int i = blockIdx.x * blockDim.x + threadIdx.x;
    if (i < N_NODES) g_deg[i] = 1;          // self loop
}

__global__ void deg_count_k(const int* __restrict__ ei) {
    int e = blockIdx.x * blockDim.x + threadIdx.x;
    if (e < N_EDGES) {
        int d = ei[N_EDGES + e];
        if (d >= 0 && d < N_NODES) atomicAdd(&g_deg[d], 1);
    }
}

__global__ void __launch_bounds__(256) bsum_k() {
    __shared__ int sh[256];
    int i = blockIdx.x * 256 + threadIdx.x;
    sh[threadIdx.x] = (i < N_NODES) ? g_deg[i] : 0;
    __syncthreads();
    for (int off = 128; off > 0; off >>= 1) {
        if (threadIdx.x < off) sh[threadIdx.x] += sh[threadIdx.x + off];
        __syncthreads();
    }
    if (threadIdx.x == 0) g_bsum[blockIdx.x] = sh[0];
}

__global__ void __launch_bounds__(256) finalize_k() {
    __shared__ int sh[256];
    __shared__ int blkoff;
    int i = blockIdx.x * 256 + threadIdx.x;
    int t = threadIdx.x;

    sh[t] = (t < NB && t < blockIdx.x) ? g_bsum[t] : 0;
    __syncthreads();
    for (int off = 128; off > 0; off >>= 1) {
        if (t < off) sh[t] += sh[t + off];
        __syncthreads();
    }
    if (t == 0) blkoff = sh[0];
    __syncthreads();

    int v = (i < N_NODES) ? g_deg[i] : 0;
    sh[t] = v;
    __syncthreads();
    for (int off = 1; off < 256; off <<= 1) {
        int x = (t >= off) ? sh[t - off] : 0;
        __syncthreads();
        sh[t] += x;
        __syncthreads();
    }
    if (i < N_NODES) {
        int start = blkoff + sh[t] - v;     // exclusive global prefix
        g_rowptr[i] = start;
        g_cursor[i] = start;
        g_dinv[i]   = rsqrtf((float)v);
        if (i == N_NODES - 1) g_rowptr[N_NODES] = start + v;
    }
}

__global__ void fill_k(const int* __restrict__ ei) {
    int e = blockIdx.x * blockDim.x + threadIdx.x;
    if (e >= TOT_EDGES) return;
    int s, d;
    if (e < N_EDGES) {
        s = ei[e];
        d = ei[N_EDGES + e];
        if (s < 0 || s >= N_NODES || d < 0 || d >= N_NODES) return;
    } else {
        s = d = e - N_EDGES;                // self loop
    }
    int pos = atomicAdd(&g_cursor[d], 1);
    g_esrc[pos]  = s;
    g_enorm[pos] = g_dinv[s] * g_dinv[d];
}

// ---------------------------------------------------------------------------
// fp16 tensor-core GEMM: g_hw[N,128] (fp16) = src @ W[128,128]
//   use_agg=0: src = x (fp32);  use_agg=1: src = g_act (fp16)
// Full-K single-stage smem; mma.m16n8k16.f32.f16.f16.f32.
// 8 warps (4M x 2N), warp tile 32x64.
// ---------------------------------------------------------------------------
extern __shared__ uint32_t s_dyn[];

__global__ void __launch_bounds__(256) gemm_f16_k(
    const float* __restrict__ A, const float* __restrict__ W, int use_agg)
{
    uint32_t* As = s_dyn;                 // [128][STRW] u32 (2 halves each)
    uint32_t* Wt = s_dyn + 128 * STRW;    // [128 n][STRW] u32, k contiguous

    const int tid   = threadIdx.x;
    const int lane  = tid & 31;
    const int wid   = tid >> 5;
    const int warpM = wid & 3;            // 0..3  -> 32-row strip
    const int warpN = wid >> 2;           // 0..1  -> 64-col strip
    const int g     = lane >> 2;          // groupID 0..7
    const int q     = lane & 3;           // thread-in-group 0..3
    const int row0  = blockIdx.x * 128;

    // ---- load A (full K=128) as fp16 ----
    if (!use_agg) {
#pragma unroll
        for (int t = 0; t < 16; t++) {
            int i  = tid + t * 256;       // 0..4095 float4 tasks
            int r  = i >> 5;              // 0..127
            int c4 = (i & 31) * 4;        // 0..124
            int grow = row0 + r;
            float4 v = make_float4(0.f, 0.f, 0.f, 0.f);
            if (grow < N_NODES)
                v = *(const float4*)(A + (size_t)grow * DIM + c4);
            uint2 p;
            *(__half2*)&p.x = __float22half2_rn(make_float2(v.x, v.y));
            *(__half2*)&p.y = __float22half2_rn(make_float2(v.z, v.w));
            *(uint2*)&As[r * STRW + c4 / 2] = p;
        }
    } else {
#pragma unroll
        for (int t = 0; t < 8; t++) {
            int i  = tid + t * 256;       // 0..2047 uint4 tasks (8 halves)
            int r  = i >> 4;              // 0..127
            int c8 = (i & 15) * 8;        // 0..120
            int grow = row0 + r;
            uint4 raw = make_uint4(0, 0, 0, 0);
            if (grow < N_NODES)
                raw = *(const uint4*)(g_act + (size_t)grow * DIM + c8);
            *(uint4*)&As[r * STRW + c8 / 2] = raw;
        }
    }

    // ---- load W transposed: Wt[n][k], coalesced LDG per k, packed STS.64 ----
#pragma unroll
    for (int t = 0; t < 16; t++) {
        int i  = tid + t * 256;           // 0..4095 tasks: (n, k-block of 4)
        int n  = i & 127;
        int kb = i >> 7;                  // 0..31
        int k0 = kb * 4;
        float w0 = W[(size_t)(k0 + 0) * DIM + n];
        float w1 = W[(size_t)(k0 + 1) * DIM + n];
        float w2 = W[(size_t)(k0 + 2) * DIM + n];
        float w3 = W[(size_t)(k0 + 3) * DIM + n];
        uint2 p;
        *(__half2*)&p.x = __float22half2_rn(make_float2(w0, w1));
        *(__half2*)&p.y = __float22half2_rn(make_float2(w2, w3));
        *(uint2*)&Wt[n * STRW + kb * 2] = p;
    }
    __syncthreads();

    // ---- mma: 8 k-steps of 16 ----
    float acc[2][8][4];
#pragma unroll
    for (int mt = 0; mt < 2; mt++)
#pragma unroll
        for (int nt = 0; nt < 8; nt++)
#pragma unroll
            for (int i = 0; i < 4; i++) acc[mt][nt][i] = 0.0f;

#pragma unroll
    for (int ks = 0; ks < 8; ++ks) {
        const int kw = ks * 8;            // u32 k-offset (16 halves)

        uint32_t a[2][4];
#pragma unroll
        for (int mt = 0; mt < 2; mt++) {
            int mb = warpM * 32 + mt * 16 + g;
            a[mt][0] = As[mb * STRW + kw + q];            // (g,   k 2q..2q+1)
            a[mt][1] = As[(mb + 8) * STRW + kw + q];      // (g+8, k 2q..2q+1)
            a[mt][2] = As[mb * STRW + kw + q + 4];        // (g,   k 2q+8..)
            a[mt][3] = As[(mb + 8) * STRW + kw + q + 4];  // (g+8, k 2q+8..)
        }
        uint32_t b[8][2];
#pragma unroll
        for (int nt = 0; nt < 8; nt++) {
            int n = warpN * 64 + nt * 8 + g;
            b[nt][0] = Wt[n * STRW + kw + q];             // (n=g, k 2q..2q+1)
            b[nt][1] = Wt[n * STRW + kw + q + 4];         // (n=g, k 2q+8..)
        }
#pragma unroll
        for (int mt = 0; mt < 2; mt++)
#pragma unroll
            for (int nt = 0; nt < 8; nt++) {
                asm volatile(
                    "mma.sync.aligned.m16n8k16.row.col.f32.f16.f16.f32 "
                    "{%0,%1,%2,%3}, {%4,%5,%6,%7}, {%8,%9}, {%0,%1,%2,%3};"
                    : "+f"(acc[mt][nt][0]), "+f"(acc[mt][nt][1]),
                      "+f"(acc[mt][nt][2]), "+f"(acc[mt][nt][3])
                    : "r"(a[mt][0]), "r"(a[mt][1]), "r"(a[mt][2]), "r"(a[mt][3]),
                      "r"(b[nt][0]), "r"(b[nt][1]));
            }
    }

    // ---- epilogue: write fp16 hw ----
#pragma unroll
    for (int mt = 0; mt < 2; mt++) {
        int r0 = row0 + warpM * 32 + mt * 16 + g;
        int r1 = r0 + 8;
#pragma unroll
        for (int nt = 0; nt < 8; nt++) {
            int col = warpN * 64 + nt * 8 + q * 2;
            if (r0 < N_NODES)
                *(__half2*)(g_hw + (size_t)r0 * DIM + col) =
                    __float22half2_rn(make_float2(acc[mt][nt][0], acc[mt][nt][1]));
            if (r1 < N_NODES)
                *(__half2*)(g_hw + (size_t)r1 * DIM + col) =
                    __float22half2_rn(make_float2(acc[mt][nt][2], acc[mt][nt][3]));
        }
    }
}

// ---------------------------------------------------------------------------
// gather: warp per dst node; lane owns 4 halves (8B) of the 256B row.
// acc = bias; acc += hw[src]*norm (fp32 math); relu;
// last=0 -> write fp16 g_act; last=1 -> write fp32 out.
// ---------------------------------------------------------------------------
__global__ void __launch_bounds__(256) gather_k(
    const float* __restrict__ bias, float* __restrict__ out, int last)
{
    int w    = (blockIdx.x * blockDim.x + threadIdx.x) >> 5;
    int lane = threadIdx.x & 31;
    if (w >= N_NODES) return;

    int beg = g_rowptr[w];
    int end = g_rowptr[w + 1];

    float4 acc = ((const float4*)bias)[lane];
    const uint2* hw2 = (const uint2*)g_hw;   // 4 halves per lane-slot

    int j = beg;
    for (; j + 3 < end; j += 4) {
        int   s0 = g_esrc[j],      s1 = g_esrc[j + 1];
        int   s2 = g_esrc[j + 2],  s3 = g_esrc[j + 3];
        float n0 = g_enorm[j],     n1 = g_enorm[j + 1];
        float n2 = g_enorm[j + 2], n3 = g_enorm[j + 3];
        uint2 r0 = hw2[s0 * 32 + lane];
        uint2 r1 = hw2[s1 * 32 + lane];
        uint2 r2 = hw2[s2 * 32 + lane];
        uint2 r3 = hw2[s3 * 32 + lane];
        float2 a0 = __half22float2(*(__half2*)&r0.x), b0 = __half22float2(*(__half2*)&r0.y);
        float2 a1 = __half22float2(*(__half2*)&r1.x), b1 = __half22float2(*(__half2*)&r1.y);
        float2 a2 = __half22float2(*(__half2*)&r2.x), b2 = __half22float2(*(__half2*)&r2.y);
        float2 a3 = __half22float2(*(__half2*)&r3.x), b3 = __half22float2(*(__half2*)&r3.y);
        acc.x += a0.x * n0; acc.y += a0.y * n0; acc.z += b0.x * n0; acc.w += b0.y * n0;
        acc.x += a1.x * n1; acc.y += a1.y * n1; acc.z += b1.x * n1; acc.w += b1.y * n1;
        acc.x += a2.x * n2; acc.y += a2.y * n2; acc.z += b2.x * n2; acc.w += b2.y * n2;
        acc.x += a3.x * n3; acc.y += a3.y * n3; acc.z += b3.x * n3; acc.w += b3.y * n3;
    }
    for (; j < end; j++) {
        int   s0 = g_esrc[j];
        float n0 = g_enorm[j];
        uint2 r0 = hw2[s0 * 32 + lane];
        float2 a0 = __half22float2(*(__half2*)&r0.x), b0 = __half22float2(*(__half2*)&r0.y);
        acc.x += a0.x * n0; acc.y += a0.y * n0; acc.z += b0.x * n0; acc.w += b0.y * n0;
    }

    acc.x = fmaxf(acc.x, 0.f); acc.y = fmaxf(acc.y, 0.f);
    acc.z = fmaxf(acc.z, 0.f); acc.w = fmaxf(acc.w, 0.f);

    if (last) {
        ((float4*)out)[w * 32 + lane] = acc;
    } else {
        uint2 o;
        *(__half2*)&o.x = __float22half2_rn(make_float2(acc.x, acc.y));
        *(__half2*)&o.y = __float22half2_rn(make_float2(acc.z, acc.w));
        ((uint2*)g_act)[w * 32 + lane] = o;
    }
}

// ---------------------------------------------------------------------------
extern "C" void kernel_launch(void* const* d_in, const int* in_sizes, int n_in,
                              void* d_out, int out_size)
{
    const float* x  = (const float*)d_in[0];
    const int*   ei = (const int*)d_in[1];     // edge_index int32 [2, E]
    const float* W0 = (const float*)d_in[2];
    const float* b0 = (const float*)d_in[3];
    const float* W1 = (const float*)d_in[4];
    const float* b1 = (const float*)d_in[5];
    const float* W2 = (const float*)d_in[6];
    const float* b2 = (const float*)d_in[7];
    float* out = (float*)d_out;

    static int smem_set = 0;
    if (!smem_set) {
        cudaFuncSetAttribute(gemm_f16_k,
            cudaFuncAttributeMaxDynamicSharedMemorySize, SMEM_BYTES);
        smem_set = 1;
    }

    const int edgeBlocks = (N_EDGES + 255) / 256;
    const int totBlocks  = (TOT_EDGES + 255) / 256;
    const int gemmBlocks = (N_NODES + 127) / 128;
    const int gathBlocks = (N_NODES * 32 + 255) / 256;   // warp per node

    // CSR build (once; reused by all 3 layers)
    deg_init_k <<<NB, 256>>>();
    deg_count_k<<<edgeBlocks, 256>>>(ei);
    bsum_k     <<<NB, 256>>>();
    finalize_k <<<NB, 256>>>();
    fill_k     <<<totBlocks, 256>>>(ei);

    // layer 0: hw = x @ W0 ; act = relu(gather(hw) + b0)
    gemm_f16_k<<<gemmBlocks, 256, SMEM_BYTES>>>(x, W0, 0);
    gather_k  <<<gathBlocks, 256>>>(b0, out, 0);
    // layer 1: hw = act @ W1 ; act = relu(gather(hw) + b1)
    gemm_f16_k<<<gemmBlocks, 256, SMEM_BYTES>>>(x, W1, 1);
    gather_k  <<<gathBlocks, 256>>>(b1, out, 0);
    // layer 2: hw = act @ W2 ; out = relu(gather(hw) + b2)
    gemm_f16_k<<<gemmBlocks, 256, SMEM_BYTES>>>(x, W2, 1);
    gather_k  <<<gathBlocks, 256>>>(b2, out, 1);
}